// round 1
// baseline (speedup 1.0000x reference)
#include <cuda_runtime.h>
#include <cuda_bf16.h>

// ---------------- problem constants (fixed-shape problem) ----------------
#define N_OBJ   20000
#define N_ROOM  500
#define N_ATTR  2000
#define F_IN    300
#define F4_IN   75          // 300/4
#define HDIM    512
#define F4_H    128         // 512/4
#define E_OO_C  640000
#define E_RO_C  50000
#define E_AO_C  100000

// ---------------- scratch (device globals: no allocation allowed) --------
struct __align__(16) Scratch {
    // float4-accessed arrays first (16B-aligned offsets)
    float agg_oo[N_OBJ * F_IN];
    float agg_ro[N_OBJ * F_IN];
    float agg_ao[N_OBJ * F_IN];
    float hsrc2[N_OBJ * HDIM];     // h_obj * ns_oo (conv2 source, pre-scaled)
    float agg2 [N_OBJ * HDIM];
    // norms
    float ns_oo[N_OBJ];  float nd_oo[N_OBJ];
    float ns_ro[N_ROOM]; float nd_ro[N_OBJ];
    float ns_ao[N_ATTR]; float nd_ao[N_OBJ];
    // degrees
    int deg_out_oo[N_OBJ];  int deg_in_oo[N_OBJ];
    int deg_out_ro[N_ROOM]; int deg_in_ro[N_OBJ];
    int deg_out_ao[N_ATTR]; int deg_in_ao[N_OBJ];
    // CSR
    int off_oo[N_OBJ + 1]; int off_ro[N_OBJ + 1]; int off_ao[N_OBJ + 1];
    int cur_oo[N_OBJ];     int cur_ro[N_OBJ];     int cur_ao[N_OBJ];
    int csr_oo[E_OO_C];    int csr_ro[E_RO_C];    int csr_ao[E_AO_C];
};
__device__ Scratch g;

// ---------------- setup kernels ------------------------------------------
__global__ void zero_degs_kernel() {
    int i = blockIdx.x * blockDim.x + threadIdx.x;
    if (i < N_OBJ) {
        g.deg_out_oo[i] = 0; g.deg_in_oo[i] = 0;
        g.deg_in_ro[i] = 0;  g.deg_in_ao[i] = 0;
        if (i < N_ROOM) g.deg_out_ro[i] = 0;
        if (i < N_ATTR) g.deg_out_ao[i] = 0;
    }
}

__global__ void count_deg_kernel(int rel, const int* __restrict__ src,
                                 const int* __restrict__ dst, int E) {
    int* dout; int* din;
    if (rel == 0)      { dout = g.deg_out_oo; din = g.deg_in_oo; }
    else if (rel == 1) { dout = g.deg_out_ro; din = g.deg_in_ro; }
    else               { dout = g.deg_out_ao; din = g.deg_in_ao; }
    int e = blockIdx.x * blockDim.x + threadIdx.x;
    if (e < E) {
        atomicAdd(&dout[src[e]], 1);
        atomicAdd(&din[dst[e]], 1);
    }
}

__global__ void compute_norms_kernel() {
    int i = blockIdx.x * blockDim.x + threadIdx.x;
    if (i < N_OBJ) {
        g.ns_oo[i] = rsqrtf(fmaxf((float)g.deg_out_oo[i], 1.f));
        g.nd_oo[i] = rsqrtf(fmaxf((float)g.deg_in_oo[i], 1.f));
        g.nd_ro[i] = rsqrtf(fmaxf((float)g.deg_in_ro[i], 1.f));
        g.nd_ao[i] = rsqrtf(fmaxf((float)g.deg_in_ao[i], 1.f));
        if (i < N_ROOM) g.ns_ro[i] = rsqrtf(fmaxf((float)g.deg_out_ro[i], 1.f));
        if (i < N_ATTR) g.ns_ao[i] = rsqrtf(fmaxf((float)g.deg_out_ao[i], 1.f));
    }
}

// Single-block exclusive scan over N_OBJ degrees -> offsets (+ cursor copy).
__global__ void scan_offsets_kernel(int rel) {
    __shared__ int csum[1025];
    const int n = N_OBJ, T = 1024;
    const int* deg; int* off; int* cur;
    if (rel == 0)      { deg = g.deg_in_oo; off = g.off_oo; cur = g.cur_oo; }
    else if (rel == 1) { deg = g.deg_in_ro; off = g.off_ro; cur = g.cur_ro; }
    else               { deg = g.deg_in_ao; off = g.off_ao; cur = g.cur_ao; }
    int t = threadIdx.x;
    int chunk = (n + T - 1) / T;
    int start = min(t * chunk, n);
    int end   = min(start + chunk, n);
    int s = 0;
    for (int i = start; i < end; i++) s += deg[i];
    csum[t + 1] = s;
    if (t == 0) csum[0] = 0;
    __syncthreads();
    if (t == 0) {
        int acc = 0;
        for (int i = 1; i <= T; i++) { acc += csum[i]; csum[i] = acc; }
    }
    __syncthreads();
    int run = csum[t];
    for (int i = start; i < end; i++) { off[i] = run; cur[i] = run; run += deg[i]; }
    if (t == 0) off[n] = csum[T];
}

__global__ void fill_csr_kernel(int rel, const int* __restrict__ src,
                                const int* __restrict__ dst, int E) {
    int* cur; int* csr;
    if (rel == 0)      { cur = g.cur_oo; csr = g.csr_oo; }
    else if (rel == 1) { cur = g.cur_ro; csr = g.csr_ro; }
    else               { cur = g.cur_ao; csr = g.csr_ao; }
    int e = blockIdx.x * blockDim.x + threadIdx.x;
    if (e < E) {
        int p = atomicAdd(&cur[dst[e]], 1);
        csr[p] = src[e];
    }
}

// ---------------- aggregation (gather over CSR) --------------------------
__device__ __forceinline__ void fma4(float4& acc, float f, const float4 v) {
    acc.x = fmaf(f, v.x, acc.x); acc.y = fmaf(f, v.y, acc.y);
    acc.z = fmaf(f, v.z, acc.z); acc.w = fmaf(f, v.w, acc.w);
}

// conv1: one CTA per dst node, lane = float4 chunk of F_IN
__global__ void agg_conv1_kernel(int rel, const float4* __restrict__ feat) {
    const int* off; const int* csr; const float* ns; float4* out;
    if (rel == 0)      { off = g.off_oo; csr = g.csr_oo; ns = g.ns_oo; out = (float4*)g.agg_oo; }
    else if (rel == 1) { off = g.off_ro; csr = g.csr_ro; ns = g.ns_ro; out = (float4*)g.agg_ro; }
    else               { off = g.off_ao; csr = g.csr_ao; ns = g.ns_ao; out = (float4*)g.agg_ao; }
    int d = blockIdx.x;
    int c = threadIdx.x;
    if (c >= F4_IN) return;
    int beg = off[d], end = off[d + 1];
    float4 acc = {0.f, 0.f, 0.f, 0.f};
    int e = beg;
    for (; e + 4 <= end; e += 4) {
        int s0 = csr[e], s1 = csr[e+1], s2 = csr[e+2], s3 = csr[e+3];
        float f0 = ns[s0], f1 = ns[s1], f2 = ns[s2], f3 = ns[s3];
        float4 v0 = feat[(long)s0 * F4_IN + c];
        float4 v1 = feat[(long)s1 * F4_IN + c];
        float4 v2 = feat[(long)s2 * F4_IN + c];
        float4 v3 = feat[(long)s3 * F4_IN + c];
        fma4(acc, f0, v0); fma4(acc, f1, v1); fma4(acc, f2, v2); fma4(acc, f3, v3);
    }
    for (; e < end; e++) {
        int s = csr[e];
        fma4(acc, ns[s], feat[(long)s * F4_IN + c]);
    }
    out[(long)d * F4_IN + c] = acc;
}

// conv2: same pattern, F4_H chunks, source already pre-scaled by ns_oo
__global__ void agg_conv2_kernel() {
    int d = blockIdx.x;
    int c = threadIdx.x;             // 128 threads == F4_H
    const float4* feat = (const float4*)g.hsrc2;
    int beg = g.off_oo[d], end = g.off_oo[d + 1];
    float4 acc = {0.f, 0.f, 0.f, 0.f};
    int e = beg;
    for (; e + 4 <= end; e += 4) {
        int s0 = g.csr_oo[e], s1 = g.csr_oo[e+1], s2 = g.csr_oo[e+2], s3 = g.csr_oo[e+3];
        float4 v0 = feat[(long)s0 * F4_H + c];
        float4 v1 = feat[(long)s1 * F4_H + c];
        float4 v2 = feat[(long)s2 * F4_H + c];
        float4 v3 = feat[(long)s3 * F4_H + c];
        acc.x += v0.x + v1.x + v2.x + v3.x;
        acc.y += v0.y + v1.y + v2.y + v3.y;
        acc.z += v0.z + v1.z + v2.z + v3.z;
        acc.w += v0.w + v1.w + v2.w + v3.w;
    }
    for (; e < end; e++) {
        int s = g.csr_oo[e];
        float4 v = feat[(long)s * F4_H + c];
        acc.x += v.x; acc.y += v.y; acc.z += v.z; acc.w += v.w;
    }
    ((float4*)g.agg2)[(long)d * F4_H + c] = acc;
}

// ---------------- GEMMs (fp32 tiled, 128x64x8, 256 thr, 8x4 microtile) ---
#define BM 128
#define BN 64
#define BK 8

// conv1: hsrc2[m,n] = (ns_oo[m]/3) * sum_rel relu(nd_rel[m]*(agg_rel[m,:]@W_rel)[n] + b_rel[n])
__global__ __launch_bounds__(256) void gemm_conv1_kernel(
    const float* __restrict__ W1i, const float* __restrict__ W1b,
    const float* __restrict__ b1i, const float* __restrict__ b1b)
{
    __shared__ float As[BK][BM];
    __shared__ float Bs[BK][BN];
    const int M = N_OBJ, K = F_IN;
    int bm = blockIdx.x * BM;
    int bn = blockIdx.y * BN;
    int tid = threadIdx.x;
    int tx = tid & 15;          // col group (4 cols)
    int ty = tid >> 4;          // row group (8 rows)
    int lrow = tid >> 1;        // A load: row 0..127
    int lk   = (tid & 1) * 4;   // A load: k offset 0/4
    int brow = tid >> 5;        // B load: row 0..7
    int bcol = (tid & 31) * 2;  // B load: col (float2)

    float res[8][4] = {};

    for (int rel = 0; rel < 3; rel++) {
        const float* A    = (rel == 0) ? g.agg_oo : (rel == 1) ? g.agg_ro : g.agg_ao;
        const float* W    = (rel == 2) ? W1b : W1i;
        const float* bias = (rel == 2) ? b1b : b1i;
        const float* nd   = (rel == 0) ? g.nd_oo : (rel == 1) ? g.nd_ro : g.nd_ao;

        float acc[8][4] = {};
        for (int k0 = 0; k0 < K; k0 += BK) {
            float4 av = {0.f, 0.f, 0.f, 0.f};
            int m = bm + lrow;
            int k = k0 + lk;
            if (m < M && k < K) av = *(const float4*)&A[(long)m * K + k];
            As[lk + 0][lrow] = av.x; As[lk + 1][lrow] = av.y;
            As[lk + 2][lrow] = av.z; As[lk + 3][lrow] = av.w;

            int kb = k0 + brow;
            float2 bv = {0.f, 0.f};
            if (kb < K) bv = *(const float2*)&W[(long)kb * HDIM + bn + bcol];
            Bs[brow][bcol] = bv.x; Bs[brow][bcol + 1] = bv.y;
            __syncthreads();
            #pragma unroll
            for (int kk = 0; kk < BK; kk++) {
                float a[8], b[4];
                *(float4*)&a[0] = *(const float4*)&As[kk][ty * 8];
                *(float4*)&a[4] = *(const float4*)&As[kk][ty * 8 + 4];
                *(float4*)&b[0] = *(const float4*)&Bs[kk][tx * 4];
                #pragma unroll
                for (int i = 0; i < 8; i++)
                    #pragma unroll
                    for (int j = 0; j < 4; j++)
                        acc[i][j] = fmaf(a[i], b[j], acc[i][j]);
            }
            __syncthreads();
        }
        #pragma unroll
        for (int i = 0; i < 8; i++) {
            int m = bm + ty * 8 + i;
            if (m < M) {
                float ndv = nd[m];
                #pragma unroll
                for (int j = 0; j < 4; j++) {
                    int n = bn + tx * 4 + j;
                    float v = fmaf(ndv, acc[i][j], bias[n]);
                    res[i][j] += fmaxf(v, 0.f);
                }
            }
        }
    }
    #pragma unroll
    for (int i = 0; i < 8; i++) {
        int m = bm + ty * 8 + i;
        if (m < M) {
            float s = g.ns_oo[m] * (1.f / 3.f);
            float4 o;
            o.x = res[i][0] * s; o.y = res[i][1] * s;
            o.z = res[i][2] * s; o.w = res[i][3] * s;
            *(float4*)&g.hsrc2[(long)m * HDIM + bn + tx * 4] = o;
        }
    }
}

// conv2: out[b,m,n] = nd_oo[m]*(agg2[m,:]@W2)[n] + b2[n], broadcast over b
__global__ __launch_bounds__(256) void gemm_conv2_kernel(
    const float* __restrict__ W2, const float* __restrict__ b2,
    float* __restrict__ out, int B)
{
    __shared__ float As[BK][BM];
    __shared__ float Bs[BK][BN];
    const int M = N_OBJ, K = HDIM;
    int bm = blockIdx.x * BM;
    int bn = blockIdx.y * BN;
    int tid = threadIdx.x;
    int tx = tid & 15;
    int ty = tid >> 4;
    int lrow = tid >> 1;
    int lk   = (tid & 1) * 4;
    int brow = tid >> 5;
    int bcol = (tid & 31) * 2;

    const float* A = g.agg2;
    float acc[8][4] = {};
    for (int k0 = 0; k0 < K; k0 += BK) {
        float4 av = {0.f, 0.f, 0.f, 0.f};
        int m = bm + lrow;
        if (m < M) av = *(const float4*)&A[(long)m * K + k0 + lk];
        As[lk + 0][lrow] = av.x; As[lk + 1][lrow] = av.y;
        As[lk + 2][lrow] = av.z; As[lk + 3][lrow] = av.w;

        float2 bv = *(const float2*)&W2[(long)(k0 + brow) * HDIM + bn + bcol];
        Bs[brow][bcol] = bv.x; Bs[brow][bcol + 1] = bv.y;
        __syncthreads();
        #pragma unroll
        for (int kk = 0; kk < BK; kk++) {
            float a[8], b[4];
            *(float4*)&a[0] = *(const float4*)&As[kk][ty * 8];
            *(float4*)&a[4] = *(const float4*)&As[kk][ty * 8 + 4];
            *(float4*)&b[0] = *(const float4*)&Bs[kk][tx * 4];
            #pragma unroll
            for (int i = 0; i < 8; i++)
                #pragma unroll
                for (int j = 0; j < 4; j++)
                    acc[i][j] = fmaf(a[i], b[j], acc[i][j]);
        }
        __syncthreads();
    }
    #pragma unroll
    for (int i = 0; i < 8; i++) {
        int m = bm + ty * 8 + i;
        if (m < M) {
            float ndv = g.nd_oo[m];
            int n = bn + tx * 4;
            float4 o;
            o.x = fmaf(ndv, acc[i][0], b2[n + 0]);
            o.y = fmaf(ndv, acc[i][1], b2[n + 1]);
            o.z = fmaf(ndv, acc[i][2], b2[n + 2]);
            o.w = fmaf(ndv, acc[i][3], b2[n + 3]);
            for (int b = 0; b < B; b++)
                *(float4*)&out[(((long)b * M) + m) * HDIM + n] = o;
        }
    }
}

// ---------------- launch --------------------------------------------------
extern "C" void kernel_launch(void* const* d_in, const int* in_sizes, int n_in,
                              void* d_out, int out_size) {
    const float* feat_obj  = (const float*)d_in[1];
    const float* feat_room = (const float*)d_in[2];
    const float* feat_attr = (const float*)d_in[3];
    const float* W1i = (const float*)d_in[4];
    const float* b1i = (const float*)d_in[5];
    const float* W1b = (const float*)d_in[6];
    const float* b1b = (const float*)d_in[7];
    const float* W2  = (const float*)d_in[8];
    const float* b2  = (const float*)d_in[9];
    const int* src_oo = (const int*)d_in[10];
    const int* dst_oo = (const int*)d_in[11];
    const int* src_ro = (const int*)d_in[12];
    const int* dst_ro = (const int*)d_in[13];
    const int* src_ao = (const int*)d_in[14];
    const int* dst_ao = (const int*)d_in[15];
    int E_oo = in_sizes[10], E_ro = in_sizes[12], E_ao = in_sizes[14];
    float* out = (float*)d_out;
    int B = out_size / (N_OBJ * HDIM);

    // degrees + norms
    zero_degs_kernel<<<(N_OBJ + 255) / 256, 256>>>();
    count_deg_kernel<<<(E_oo + 255) / 256, 256>>>(0, src_oo, dst_oo, E_oo);
    count_deg_kernel<<<(E_ro + 255) / 256, 256>>>(1, src_ro, dst_ro, E_ro);
    count_deg_kernel<<<(E_ao + 255) / 256, 256>>>(2, src_ao, dst_ao, E_ao);
    compute_norms_kernel<<<(N_OBJ + 255) / 256, 256>>>();

    // CSR build (counting sort by dst)
    scan_offsets_kernel<<<1, 1024>>>(0);
    scan_offsets_kernel<<<1, 1024>>>(1);
    scan_offsets_kernel<<<1, 1024>>>(2);
    fill_csr_kernel<<<(E_oo + 255) / 256, 256>>>(0, src_oo, dst_oo, E_oo);
    fill_csr_kernel<<<(E_ro + 255) / 256, 256>>>(1, src_ro, dst_ro, E_ro);
    fill_csr_kernel<<<(E_ao + 255) / 256, 256>>>(2, src_ao, dst_ao, E_ao);

    // conv1: aggregate (300-dim) then fused 3-relation GEMM -> hsrc2
    agg_conv1_kernel<<<N_OBJ, 96>>>(0, (const float4*)feat_obj);
    agg_conv1_kernel<<<N_OBJ, 96>>>(1, (const float4*)feat_room);
    agg_conv1_kernel<<<N_OBJ, 96>>>(2, (const float4*)feat_attr);
    dim3 ggrid((N_OBJ + BM - 1) / BM, HDIM / BN);
    gemm_conv1_kernel<<<ggrid, 256>>>(W1i, W1b, b1i, b1b);

    // conv2: aggregate (512-dim) then GEMM + broadcast epilogue
    agg_conv2_kernel<<<N_OBJ, 128>>>();
    gemm_conv2_kernel<<<ggrid, 256>>>(W2, b2, out, B);
}

// round 3
// speedup vs baseline: 1.5298x; 1.5298x over previous
#include <cuda_runtime.h>
#include <cuda_bf16.h>
#include <cstdint>

// ---------------- problem constants --------------------------------------
#define N_OBJ   20000
#define N_ROOM  500
#define N_ATTR  2000
#define F_IN    300
#define F4_IN   75
#define KPAD1   320           // F_IN padded to 64-multiple
#define HDIM    512
#define F4_H    128
#define E_OO_C  640000
#define E_RO_C  50000
#define E_AO_C  100000

#define KC      32            // K per pipeline chunk
#define ASTRIDE 40            // bf16 elems per smem row (32 + 8 pad) -> 80B rows
#define BUFB    20480         // bytes per double-buffer slot (A 10240 + B 10240)

// ---------------- scratch ------------------------------------------------
struct __align__(16) Scratch {
    __nv_bfloat16 a1h[3 * N_OBJ * KPAD1];
    __nv_bfloat16 a1l[3 * N_OBJ * KPAD1];
    __nv_bfloat16 a2h[N_OBJ * HDIM];
    __nv_bfloat16 a2l[N_OBJ * HDIM];
    __nv_bfloat16 w1ih[HDIM * KPAD1], w1il[HDIM * KPAD1];
    __nv_bfloat16 w1bh[HDIM * KPAD1], w1bl[HDIM * KPAD1];
    __nv_bfloat16 w2h[HDIM * HDIM],  w2l[HDIM * HDIM];
    float hsrc2[N_OBJ * HDIM];
    float ns_oo[N_OBJ];  float nd_oo[N_OBJ];
    float ns_ro[N_ROOM]; float nd_ro[N_OBJ];
    float ns_ao[N_ATTR]; float nd_ao[N_OBJ];
    int deg_out_oo[N_OBJ];  int deg_in_oo[N_OBJ];
    int deg_out_ro[N_ROOM]; int deg_in_ro[N_OBJ];
    int deg_out_ao[N_ATTR]; int deg_in_ao[N_OBJ];
    int off_oo[N_OBJ + 1]; int off_ro[N_OBJ + 1]; int off_ao[N_OBJ + 1];
    int cur_oo[N_OBJ];     int cur_ro[N_OBJ];     int cur_ao[N_OBJ];
    int csr_oo[E_OO_C];    int csr_ro[E_RO_C];    int csr_ao[E_AO_C];
};
__device__ Scratch g;

// ---------------- helpers ------------------------------------------------
__device__ __forceinline__ uint32_t smem_u32(const void* p) {
    uint32_t a;
    asm("{ .reg .u64 t; cvta.to.shared.u64 t, %1; cvt.u32.u64 %0, t; }" : "=r"(a) : "l"(p));
    return a;
}
__device__ __forceinline__ void cp16(uint32_t dst, const void* src, int sz) {
    asm volatile("cp.async.cg.shared.global [%0], [%1], 16, %2;"
                 :: "r"(dst), "l"(src), "r"(sz) : "memory");
}
__device__ __forceinline__ void ldsm4(uint32_t* r, uint32_t addr) {
    asm volatile("ldmatrix.sync.aligned.m8n8.x4.shared.b16 {%0,%1,%2,%3}, [%4];"
                 : "=r"(r[0]), "=r"(r[1]), "=r"(r[2]), "=r"(r[3]) : "r"(addr));
}
__device__ __forceinline__ void mma16816(float* d, const uint32_t* a, const uint32_t* b) {
    asm volatile("mma.sync.aligned.m16n8k16.row.col.f32.bf16.bf16.f32 "
                 "{%0,%1,%2,%3}, {%4,%5,%6,%7}, {%8,%9}, {%0,%1,%2,%3};"
                 : "+f"(d[0]), "+f"(d[1]), "+f"(d[2]), "+f"(d[3])
                 : "r"(a[0]), "r"(a[1]), "r"(a[2]), "r"(a[3]), "r"(b[0]), "r"(b[1]));
}
__device__ __forceinline__ void split_bf16(float v, __nv_bfloat16& h, __nv_bfloat16& l) {
    h = __float2bfloat16(v);
    l = __float2bfloat16(v - __bfloat162float(h));
}

// ---------------- setup kernels ------------------------------------------
__global__ void zero_degs_kernel() {
    int i = blockIdx.x * blockDim.x + threadIdx.x;
    if (i < N_OBJ) {
        g.deg_out_oo[i] = 0; g.deg_in_oo[i] = 0;
        g.deg_in_ro[i] = 0;  g.deg_in_ao[i] = 0;
        if (i < N_ROOM) g.deg_out_ro[i] = 0;
        if (i < N_ATTR) g.deg_out_ao[i] = 0;
    }
}

__global__ void count_deg_kernel(int rel, const int* __restrict__ src,
                                 const int* __restrict__ dst, int E) {
    int* dout; int* din;
    if (rel == 0)      { dout = g.deg_out_oo; din = g.deg_in_oo; }
    else if (rel == 1) { dout = g.deg_out_ro; din = g.deg_in_ro; }
    else               { dout = g.deg_out_ao; din = g.deg_in_ao; }
    int e = blockIdx.x * blockDim.x + threadIdx.x;
    if (e < E) {
        atomicAdd(&dout[src[e]], 1);
        atomicAdd(&din[dst[e]], 1);
    }
}

__global__ void compute_norms_kernel() {
    int i = blockIdx.x * blockDim.x + threadIdx.x;
    if (i < N_OBJ) {
        g.ns_oo[i] = rsqrtf(fmaxf((float)g.deg_out_oo[i], 1.f));
        g.nd_oo[i] = rsqrtf(fmaxf((float)g.deg_in_oo[i], 1.f));
        g.nd_ro[i] = rsqrtf(fmaxf((float)g.deg_in_ro[i], 1.f));
        g.nd_ao[i] = rsqrtf(fmaxf((float)g.deg_in_ao[i], 1.f));
        if (i < N_ROOM) g.ns_ro[i] = rsqrtf(fmaxf((float)g.deg_out_ro[i], 1.f));
        if (i < N_ATTR) g.ns_ao[i] = rsqrtf(fmaxf((float)g.deg_out_ao[i], 1.f));
    }
}

__global__ void scan_offsets_kernel(int rel) {
    __shared__ int csum[1025];
    const int n = N_OBJ, T = 1024;
    const int* deg; int* off; int* cur;
    if (rel == 0)      { deg = g.deg_in_oo; off = g.off_oo; cur = g.cur_oo; }
    else if (rel == 1) { deg = g.deg_in_ro; off = g.off_ro; cur = g.cur_ro; }
    else               { deg = g.deg_in_ao; off = g.off_ao; cur = g.cur_ao; }
    int t = threadIdx.x;
    int chunk = (n + T - 1) / T;
    int start = min(t * chunk, n);
    int end   = min(start + chunk, n);
    int s = 0;
    for (int i = start; i < end; i++) s += deg[i];
    csum[t + 1] = s;
    if (t == 0) csum[0] = 0;
    __syncthreads();
    if (t == 0) {
        int acc = 0;
        for (int i = 1; i <= T; i++) { acc += csum[i]; csum[i] = acc; }
    }
    __syncthreads();
    int run = csum[t];
    for (int i = start; i < end; i++) { off[i] = run; cur[i] = run; run += deg[i]; }
    if (t == 0) off[n] = csum[T];
}

__global__ void fill_csr_kernel(int rel, const int* __restrict__ src,
                                const int* __restrict__ dst, int E) {
    int* cur; int* csr;
    if (rel == 0)      { cur = g.cur_oo; csr = g.csr_oo; }
    else if (rel == 1) { cur = g.cur_ro; csr = g.csr_ro; }
    else               { cur = g.cur_ao; csr = g.csr_ao; }
    int e = blockIdx.x * blockDim.x + threadIdx.x;
    if (e < E) {
        int p = atomicAdd(&cur[dst[e]], 1);
        csr[p] = src[e];
    }
}

// Transpose + pad + bf16-split weights: Wt[n][k] = W[k][n]
__global__ void prep_weights_kernel(const float* __restrict__ W1i,
                                    const float* __restrict__ W1b,
                                    const float* __restrict__ W2) {
    int i = blockIdx.x * blockDim.x + threadIdx.x;
    const int NW1 = HDIM * KPAD1;
    if (i < NW1) {
        int n = i / KPAD1, k = i % KPAD1;
        float wi = (k < F_IN) ? W1i[k * HDIM + n] : 0.f;
        float wb = (k < F_IN) ? W1b[k * HDIM + n] : 0.f;
        split_bf16(wi, g.w1ih[i], g.w1il[i]);
        split_bf16(wb, g.w1bh[i], g.w1bl[i]);
    } else {
        int j = i - NW1;
        if (j < HDIM * HDIM) {
            int n = j / HDIM, k = j % HDIM;
            split_bf16(W2[k * HDIM + n], g.w2h[j], g.w2l[j]);
        }
    }
}

// ---------------- aggregation --------------------------------------------
__device__ __forceinline__ void fma4(float4& acc, float f, const float4 v) {
    acc.x = fmaf(f, v.x, acc.x); acc.y = fmaf(f, v.y, acc.y);
    acc.z = fmaf(f, v.z, acc.z); acc.w = fmaf(f, v.w, acc.w);
}

__global__ void agg_conv1_kernel(int rel, const float4* __restrict__ feat) {
    const int* off; const int* csr; const float* ns;
    if (rel == 0)      { off = g.off_oo; csr = g.csr_oo; ns = g.ns_oo; }
    else if (rel == 1) { off = g.off_ro; csr = g.csr_ro; ns = g.ns_ro; }
    else               { off = g.off_ao; csr = g.csr_ao; ns = g.ns_ao; }
    int d = blockIdx.x;
    int c = threadIdx.x;          // 80 threads: 75 data + 5 zero-pad chunks
    float4 acc = {0.f, 0.f, 0.f, 0.f};
    if (c < F4_IN) {
        int beg = off[d], end = off[d + 1];
        int e = beg;
        for (; e + 4 <= end; e += 4) {
            int s0 = csr[e], s1 = csr[e+1], s2 = csr[e+2], s3 = csr[e+3];
            float f0 = ns[s0], f1 = ns[s1], f2 = ns[s2], f3 = ns[s3];
            float4 v0 = feat[(size_t)s0 * F4_IN + c];
            float4 v1 = feat[(size_t)s1 * F4_IN + c];
            float4 v2 = feat[(size_t)s2 * F4_IN + c];
            float4 v3 = feat[(size_t)s3 * F4_IN + c];
            fma4(acc, f0, v0); fma4(acc, f1, v1); fma4(acc, f2, v2); fma4(acc, f3, v3);
        }
        for (; e < end; e++) {
            int s = csr[e];
            fma4(acc, ns[s], feat[(size_t)s * F4_IN + c]);
        }
    }
    size_t base = (size_t)rel * N_OBJ * KPAD1 + (size_t)d * KPAD1 + c * 4;
    __nv_bfloat16 h[4], l[4];
    split_bf16(acc.x, h[0], l[0]); split_bf16(acc.y, h[1], l[1]);
    split_bf16(acc.z, h[2], l[2]); split_bf16(acc.w, h[3], l[3]);
    *(uint2*)&g.a1h[base] = *(uint2*)h;
    *(uint2*)&g.a1l[base] = *(uint2*)l;
}

__global__ void agg_conv2_kernel() {
    int d = blockIdx.x;
    int c = threadIdx.x;          // 128 threads
    const float4* feat = (const float4*)g.hsrc2;
    int beg = g.off_oo[d], end = g.off_oo[d + 1];
    float4 acc = {0.f, 0.f, 0.f, 0.f};
    int e = beg;
    for (; e + 4 <= end; e += 4) {
        int s0 = g.csr_oo[e], s1 = g.csr_oo[e+1], s2 = g.csr_oo[e+2], s3 = g.csr_oo[e+3];
        float4 v0 = feat[(size_t)s0 * F4_H + c];
        float4 v1 = feat[(size_t)s1 * F4_H + c];
        float4 v2 = feat[(size_t)s2 * F4_H + c];
        float4 v3 = feat[(size_t)s3 * F4_H + c];
        acc.x += v0.x + v1.x + v2.x + v3.x;
        acc.y += v0.y + v1.y + v2.y + v3.y;
        acc.z += v0.z + v1.z + v2.z + v3.z;
        acc.w += v0.w + v1.w + v2.w + v3.w;
    }
    for (; e < end; e++) {
        int s = g.csr_oo[e];
        float4 v = feat[(size_t)s * F4_H + c];
        acc.x += v.x; acc.y += v.y; acc.z += v.z; acc.w += v.w;
    }
    size_t base = (size_t)d * HDIM + c * 4;
    __nv_bfloat16 h[4], l[4];
    split_bf16(acc.x, h[0], l[0]); split_bf16(acc.y, h[1], l[1]);
    split_bf16(acc.z, h[2], l[2]); split_bf16(acc.w, h[3], l[3]);
    *(uint2*)&g.a2h[base] = *(uint2*)h;
    *(uint2*)&g.a2l[base] = *(uint2*)l;
}

// ---------------- mma.sync GEMM core -------------------------------------
// CTA tile 128x128, 8 warps (wr 0..3 = M rows of 32, wc 0..1 = N cols of 64)
// warp tile 32x64, mma m16n8k16 bf16, cp.async double buffer, K-chunk 32.

__device__ __forceinline__ void issue_chunk(
    const __nv_bfloat16* __restrict__ A, const __nv_bfloat16* __restrict__ B,
    int lda, int ldb, int bm, int Mvalid, int bn, int koff,
    uint32_t sa, uint32_t sb, int tid)
{
    #pragma unroll
    for (int j = 0; j < 2; j++) {
        int i = tid + j * 256;          // 0..511
        int r = i >> 2, q = i & 3;      // row, 16B quarter
        cp16(sa + (r * ASTRIDE + q * 8) * 2,
             A + (size_t)(bm + r) * lda + koff + q * 8,
             (bm + r < Mvalid) ? 16 : 0);
        cp16(sb + (r * ASTRIDE + q * 8) * 2,
             B + (size_t)(bn + r) * ldb + koff + q * 8, 16);
    }
    asm volatile("cp.async.commit_group;" ::: "memory");
}

__device__ __forceinline__ void compute_chunk(uint32_t sa, uint32_t sb,
                                              int lane, int wr, int wc,
                                              float acc[2][8][4])
{
    // ldmatrix lane addressing (matrix index m = lane>>3)
    uint32_t arow = wr * 32 + ((lane >> 3) & 1) * 8 + (lane & 7);
    uint32_t acol = (lane >> 4) * 8;
    uint32_t abase = sa + (arow * ASTRIDE + acol) * 2;
    uint32_t nrow = wc * 64 + (lane >> 4) * 8 + (lane & 7);
    uint32_t kcol = ((lane >> 3) & 1) * 8;
    uint32_t bbase = sb + (nrow * ASTRIDE + kcol) * 2;

    #pragma unroll
    for (int k16 = 0; k16 < KC; k16 += 16) {
        uint32_t a0[4], a1[4];
        ldsm4(a0, abase + k16 * 2);
        ldsm4(a1, abase + (16 * ASTRIDE + k16) * 2);
        #pragma unroll
        for (int np = 0; np < 4; np++) {
            uint32_t b[4];
            ldsm4(b, bbase + (np * 16 * ASTRIDE + k16) * 2);
            mma16816(acc[0][2*np],     a0, b);
            mma16816(acc[1][2*np],     a1, b);
            mma16816(acc[0][2*np + 1], a0, b + 2);
            mma16816(acc[1][2*np + 1], a1, b + 2);
        }
    }
}

__device__ __forceinline__ void gemm_segment(
    const __nv_bfloat16* __restrict__ A, const __nv_bfloat16* __restrict__ B,
    int K, int lda, int ldb, int bm, int Mvalid, int bn,
    uint32_t s0, float acc[2][8][4])
{
    int tid = threadIdx.x, lane = tid & 31, wr = (tid >> 5) & 3, wc = tid >> 7;
    int nc = K / KC;
    issue_chunk(A, B, lda, ldb, bm, Mvalid, bn, 0, s0, s0 + 10240, tid);
    for (int c = 0; c < nc; c++) {
        int buf = c & 1;
        uint32_t sa = s0 + buf * BUFB, sb = sa + 10240;
        if (c + 1 < nc) {
            uint32_t sa2 = s0 + (buf ^ 1) * BUFB;
            issue_chunk(A, B, lda, ldb, bm, Mvalid, bn, (c + 1) * KC, sa2, sa2 + 10240, tid);
            asm volatile("cp.async.wait_group 1;" ::: "memory");
        } else {
            asm volatile("cp.async.wait_group 0;" ::: "memory");
        }
        __syncthreads();
        compute_chunk(sa, sb, lane, wr, wc, acc);
        __syncthreads();
    }
}

// conv1: hsrc2[m,n] = (ns_oo[m]/3) * sum_rel relu(nd_rel[m]*(A_rel@W_rel)[n] + b_rel[n])
__global__ __launch_bounds__(256) void gemm_conv1_mma(
    const float* __restrict__ b1i, const float* __restrict__ b1b)
{
    __shared__ __align__(16) __nv_bfloat16 ss[2][2][128 * ASTRIDE];
    uint32_t s0 = smem_u32(ss);
    int bm = blockIdx.x * 128, bn = blockIdx.y * 128;
    int tid = threadIdx.x, lane = tid & 31, wr = (tid >> 5) & 3, wc = tid >> 7;

    float res[2][8][4] = {};

    for (int rel = 0; rel < 3; rel++) {
        const __nv_bfloat16* Ah = g.a1h + (size_t)rel * N_OBJ * KPAD1;
        const __nv_bfloat16* Al = g.a1l + (size_t)rel * N_OBJ * KPAD1;
        const __nv_bfloat16* Bh = (rel == 2) ? g.w1bh : g.w1ih;
        const __nv_bfloat16* Bl = (rel == 2) ? g.w1bl : g.w1il;
        const float* nd   = (rel == 0) ? g.nd_oo : (rel == 1) ? g.nd_ro : g.nd_ao;
        const float* bias = (rel == 2) ? b1b : b1i;

        float acc[2][8][4] = {};
        gemm_segment(Ah, Bh, KPAD1, KPAD1, KPAD1, bm, N_OBJ, bn, s0, acc);
        gemm_segment(Ah, Bl, KPAD1, KPAD1, KPAD1, bm, N_OBJ, bn, s0, acc);
        gemm_segment(Al, Bh, KPAD1, KPAD1, KPAD1, bm, N_OBJ, bn, s0, acc);

        #pragma unroll
        for (int mt = 0; mt < 2; mt++) {
            int m0 = bm + wr * 32 + mt * 16 + (lane >> 2);
            int m1 = m0 + 8;
            float nd0 = (m0 < N_OBJ) ? nd[m0] : 0.f;
            float nd1 = (m1 < N_OBJ) ? nd[m1] : 0.f;
            #pragma unroll
            for (int nt = 0; nt < 8; nt++) {
                int col = bn + wc * 64 + nt * 8 + (lane & 3) * 2;
                float bx = bias[col], by = bias[col + 1];
                res[mt][nt][0] += fmaxf(fmaf(acc[mt][nt][0], nd0, bx), 0.f);
                res[mt][nt][1] += fmaxf(fmaf(acc[mt][nt][1], nd0, by), 0.f);
                res[mt][nt][2] += fmaxf(fmaf(acc[mt][nt][2], nd1, bx), 0.f);
                res[mt][nt][3] += fmaxf(fmaf(acc[mt][nt][3], nd1, by), 0.f);
            }
        }
    }

    #pragma unroll
    for (int mt = 0; mt < 2; mt++) {
        int m0 = bm + wr * 32 + mt * 16 + (lane >> 2);
        int m1 = m0 + 8;
        float sc0 = (m0 < N_OBJ) ? g.ns_oo[m0] * (1.f / 3.f) : 0.f;
        float sc1 = (m1 < N_OBJ) ? g.ns_oo[m1] * (1.f / 3.f) : 0.f;
        #pragma unroll
        for (int nt = 0; nt < 8; nt++) {
            int col = bn + wc * 64 + nt * 8 + (lane & 3) * 2;
            if (m0 < N_OBJ)
                *(float2*)&g.hsrc2[(size_t)m0 * HDIM + col] =
                    make_float2(res[mt][nt][0] * sc0, res[mt][nt][1] * sc0);
            if (m1 < N_OBJ)
                *(float2*)&g.hsrc2[(size_t)m1 * HDIM + col] =
                    make_float2(res[mt][nt][2] * sc1, res[mt][nt][3] * sc1);
        }
    }
}

// conv2: out[b,m,n] = nd_oo[m]*(A2@W2)[n] + b2[n], broadcast over b
__global__ __launch_bounds__(256) void gemm_conv2_mma(
    const float* __restrict__ b2, float* __restrict__ out, int B)
{
    __shared__ __align__(16) __nv_bfloat16 ss[2][2][128 * ASTRIDE];
    uint32_t s0 = smem_u32(ss);
    int bm = blockIdx.x * 128, bn = blockIdx.y * 128;
    int tid = threadIdx.x, lane = tid & 31, wr = (tid >> 5) & 3, wc = tid >> 7;

    float acc[2][8][4] = {};
    gemm_segment(g.a2h, g.w2h, HDIM, HDIM, HDIM, bm, N_OBJ, bn, s0, acc);
    gemm_segment(g.a2h, g.w2l, HDIM, HDIM, HDIM, bm, N_OBJ, bn, s0, acc);
    gemm_segment(g.a2l, g.w2h, HDIM, HDIM, HDIM, bm, N_OBJ, bn, s0, acc);

    #pragma unroll
    for (int mt = 0; mt < 2; mt++) {
        int m0 = bm + wr * 32 + mt * 16 + (lane >> 2);
        int m1 = m0 + 8;
        float nd0 = (m0 < N_OBJ) ? g.nd_oo[m0] : 0.f;
        float nd1 = (m1 < N_OBJ) ? g.nd_oo[m1] : 0.f;
        #pragma unroll
        for (int nt = 0; nt < 8; nt++) {
            int col = bn + wc * 64 + nt * 8 + (lane & 3) * 2;
            float bx = b2[col], by = b2[col + 1];
            float2 v0 = make_float2(fmaf(acc[mt][nt][0], nd0, bx),
                                    fmaf(acc[mt][nt][1], nd0, by));
            float2 v1 = make_float2(fmaf(acc[mt][nt][2], nd1, bx),
                                    fmaf(acc[mt][nt][3], nd1, by));
            for (int b = 0; b < B; b++) {
                if (m0 < N_OBJ)
                    *(float2*)&out[(((size_t)b * N_OBJ) + m0) * HDIM + col] = v0;
                if (m1 < N_OBJ)
                    *(float2*)&out[(((size_t)b * N_OBJ) + m1) * HDIM + col] = v1;
            }
        }
    }
}

// ---------------- launch --------------------------------------------------
extern "C" void kernel_launch(void* const* d_in, const int* in_sizes, int n_in,
                              void* d_out, int out_size) {
    const float* feat_obj  = (const float*)d_in[1];
    const float* feat_room = (const float*)d_in[2];
    const float* feat_attr = (const float*)d_in[3];
    const float* W1i = (const float*)d_in[4];
    const float* b1i = (const float*)d_in[5];
    const float* W1b = (const float*)d_in[6];
    const float* b1b = (const float*)d_in[7];
    const float* W2  = (const float*)d_in[8];
    const float* b2  = (const float*)d_in[9];
    const int* src_oo = (const int*)d_in[10];
    const int* dst_oo = (const int*)d_in[11];
    const int* src_ro = (const int*)d_in[12];
    const int* dst_ro = (const int*)d_in[13];
    const int* src_ao = (const int*)d_in[14];
    const int* dst_ao = (const int*)d_in[15];
    int E_oo = in_sizes[10], E_ro = in_sizes[12], E_ao = in_sizes[14];
    float* out = (float*)d_out;
    int B = out_size / (N_OBJ * HDIM);

    // degrees + norms
    zero_degs_kernel<<<(N_OBJ + 255) / 256, 256>>>();
    count_deg_kernel<<<(E_oo + 255) / 256, 256>>>(0, src_oo, dst_oo, E_oo);
    count_deg_kernel<<<(E_ro + 255) / 256, 256>>>(1, src_ro, dst_ro, E_ro);
    count_deg_kernel<<<(E_ao + 255) / 256, 256>>>(2, src_ao, dst_ao, E_ao);
    compute_norms_kernel<<<(N_OBJ + 255) / 256, 256>>>();

    // CSR build
    scan_offsets_kernel<<<1, 1024>>>(0);
    scan_offsets_kernel<<<1, 1024>>>(1);
    scan_offsets_kernel<<<1, 1024>>>(2);
    fill_csr_kernel<<<(E_oo + 255) / 256, 256>>>(0, src_oo, dst_oo, E_oo);
    fill_csr_kernel<<<(E_ro + 255) / 256, 256>>>(1, src_ro, dst_ro, E_ro);
    fill_csr_kernel<<<(E_ao + 255) / 256, 256>>>(2, src_ao, dst_ao, E_ao);

    // weight transpose + bf16 split
    int prep_n = HDIM * KPAD1 + HDIM * HDIM;
    prep_weights_kernel<<<(prep_n + 255) / 256, 256>>>(W1i, W1b, W2);

    // conv1: aggregate then mma GEMM (3 relations + 3-term split fused)
    agg_conv1_kernel<<<N_OBJ, 80>>>(0, (const float4*)feat_obj);
    agg_conv1_kernel<<<N_OBJ, 80>>>(1, (const float4*)feat_room);
    agg_conv1_kernel<<<N_OBJ, 80>>>(2, (const float4*)feat_attr);
    dim3 ggrid((N_OBJ + 127) / 128, HDIM / 128);
    gemm_conv1_mma<<<ggrid, 256>>>(b1i, b1b);

    // conv2: aggregate then mma GEMM + broadcast epilogue
    agg_conv2_kernel<<<N_OBJ, 128>>>();
    gemm_conv2_mma<<<ggrid, 256>>>(b2, out, B);
}

// round 4
// speedup vs baseline: 1.9214x; 1.2560x over previous
#include <cuda_runtime.h>
#include <cuda_bf16.h>
#include <cstdint>

// ---------------- problem constants --------------------------------------
#define N_OBJ   20000
#define N_ROOM  500
#define N_ATTR  2000
#define F_IN    300
#define F4_IN   75
#define KPAD1   320           // F_IN padded to 64-multiple
#define HDIM    512
#define F4_H    128
#define E_OO_C  640000
#define E_RO_C  50000
#define E_AO_C  100000

#define KC      32            // K per pipeline chunk
#define ASTRIDE 40            // bf16 elems per smem row (32 + 8 pad) -> 80B rows
#define TILEB   10240         // bytes per 128x32 tile (128*40*2)
#define STAGEB  40960         // 4 tiles per stage
#define SMEM_PIPE (2 * STAGEB)

// ---------------- scratch ------------------------------------------------
struct __align__(16) Scratch {
    __nv_bfloat16 a1h[3 * N_OBJ * KPAD1];
    __nv_bfloat16 a1l[3 * N_OBJ * KPAD1];
    __nv_bfloat16 a2h[N_OBJ * HDIM];
    __nv_bfloat16 a2l[N_OBJ * HDIM];
    __nv_bfloat16 w1ih[HDIM * KPAD1], w1il[HDIM * KPAD1];
    __nv_bfloat16 w1bh[HDIM * KPAD1], w1bl[HDIM * KPAD1];
    __nv_bfloat16 w2h[HDIM * HDIM],  w2l[HDIM * HDIM];
    float hsrc2[N_OBJ * HDIM];
    float ns_oo[N_OBJ];  float nd_oo[N_OBJ];
    float ns_ro[N_ROOM]; float nd_ro[N_OBJ];
    float ns_ao[N_ATTR]; float nd_ao[N_OBJ];
    int deg_out_oo[N_OBJ];  int deg_in_oo[N_OBJ];
    int deg_out_ro[N_ROOM]; int deg_in_ro[N_OBJ];
    int deg_out_ao[N_ATTR]; int deg_in_ao[N_OBJ];
    int off_oo[N_OBJ + 1]; int off_ro[N_OBJ + 1]; int off_ao[N_OBJ + 1];
    int cur_oo[N_OBJ];     int cur_ro[N_OBJ];     int cur_ao[N_OBJ];
    int csr_oo[E_OO_C];    int csr_ro[E_RO_C];    int csr_ao[E_AO_C];
};
__device__ Scratch g;

// ---------------- helpers ------------------------------------------------
__device__ __forceinline__ uint32_t smem_u32(const void* p) {
    uint32_t a;
    asm("{ .reg .u64 t; cvta.to.shared.u64 t, %1; cvt.u32.u64 %0, t; }" : "=r"(a) : "l"(p));
    return a;
}
__device__ __forceinline__ void cp16(uint32_t dst, const void* src, int sz) {
    asm volatile("cp.async.cg.shared.global [%0], [%1], 16, %2;"
                 :: "r"(dst), "l"(src), "r"(sz) : "memory");
}
__device__ __forceinline__ void ldsm4(uint32_t* r, uint32_t addr) {
    asm volatile("ldmatrix.sync.aligned.m8n8.x4.shared.b16 {%0,%1,%2,%3}, [%4];"
                 : "=r"(r[0]), "=r"(r[1]), "=r"(r[2]), "=r"(r[3]) : "r"(addr));
}
__device__ __forceinline__ void mma16816(float* d, const uint32_t* a, const uint32_t* b) {
    asm volatile("mma.sync.aligned.m16n8k16.row.col.f32.bf16.bf16.f32 "
                 "{%0,%1,%2,%3}, {%4,%5,%6,%7}, {%8,%9}, {%0,%1,%2,%3};"
                 : "+f"(d[0]), "+f"(d[1]), "+f"(d[2]), "+f"(d[3])
                 : "r"(a[0]), "r"(a[1]), "r"(a[2]), "r"(a[3]), "r"(b[0]), "r"(b[1]));
}
__device__ __forceinline__ void split_bf16(float v, __nv_bfloat16& h, __nv_bfloat16& l) {
    h = __float2bfloat16(v);
    l = __float2bfloat16(v - __bfloat162float(h));
}

// ---------------- setup kernels ------------------------------------------
__global__ void zero_degs_kernel() {
    int i = blockIdx.x * blockDim.x + threadIdx.x;
    if (i < N_OBJ) {
        g.deg_out_oo[i] = 0; g.deg_in_oo[i] = 0;
        g.deg_in_ro[i] = 0;  g.deg_in_ao[i] = 0;
        if (i < N_ROOM) g.deg_out_ro[i] = 0;
        if (i < N_ATTR) g.deg_out_ao[i] = 0;
    }
}

__global__ void count_deg_all(const int* __restrict__ s0, const int* __restrict__ d0, int E0,
                              const int* __restrict__ s1, const int* __restrict__ d1, int E1,
                              const int* __restrict__ s2, const int* __restrict__ d2, int E2) {
    int rel = blockIdx.y;
    const int* src; const int* dst; int E; int* dout; int* din;
    if (rel == 0)      { src = s0; dst = d0; E = E0; dout = g.deg_out_oo; din = g.deg_in_oo; }
    else if (rel == 1) { src = s1; dst = d1; E = E1; dout = g.deg_out_ro; din = g.deg_in_ro; }
    else               { src = s2; dst = d2; E = E2; dout = g.deg_out_ao; din = g.deg_in_ao; }
    int e = blockIdx.x * blockDim.x + threadIdx.x;
    if (e < E) {
        atomicAdd(&dout[src[e]], 1);
        atomicAdd(&din[dst[e]], 1);
    }
}

__global__ void compute_norms_kernel() {
    int i = blockIdx.x * blockDim.x + threadIdx.x;
    if (i < N_OBJ) {
        g.ns_oo[i] = rsqrtf(fmaxf((float)g.deg_out_oo[i], 1.f));
        g.nd_oo[i] = rsqrtf(fmaxf((float)g.deg_in_oo[i], 1.f));
        g.nd_ro[i] = rsqrtf(fmaxf((float)g.deg_in_ro[i], 1.f));
        g.nd_ao[i] = rsqrtf(fmaxf((float)g.deg_in_ao[i], 1.f));
        if (i < N_ROOM) g.ns_ro[i] = rsqrtf(fmaxf((float)g.deg_out_ro[i], 1.f));
        if (i < N_ATTR) g.ns_ao[i] = rsqrtf(fmaxf((float)g.deg_out_ao[i], 1.f));
    }
}

__global__ void scan_offsets_all() {
    __shared__ int csum[1025];
    const int n = N_OBJ, T = 1024;
    int rel = blockIdx.x;
    const int* deg; int* off; int* cur;
    if (rel == 0)      { deg = g.deg_in_oo; off = g.off_oo; cur = g.cur_oo; }
    else if (rel == 1) { deg = g.deg_in_ro; off = g.off_ro; cur = g.cur_ro; }
    else               { deg = g.deg_in_ao; off = g.off_ao; cur = g.cur_ao; }
    int t = threadIdx.x;
    int chunk = (n + T - 1) / T;
    int start = min(t * chunk, n);
    int end   = min(start + chunk, n);
    int s = 0;
    for (int i = start; i < end; i++) s += deg[i];
    csum[t + 1] = s;
    if (t == 0) csum[0] = 0;
    __syncthreads();
    if (t == 0) {
        int acc = 0;
        for (int i = 1; i <= T; i++) { acc += csum[i]; csum[i] = acc; }
    }
    __syncthreads();
    int run = csum[t];
    for (int i = start; i < end; i++) { off[i] = run; cur[i] = run; run += deg[i]; }
    if (t == 0) off[n] = csum[T];
}

__global__ void fill_csr_all(const int* __restrict__ s0, const int* __restrict__ d0, int E0,
                             const int* __restrict__ s1, const int* __restrict__ d1, int E1,
                             const int* __restrict__ s2, const int* __restrict__ d2, int E2) {
    int rel = blockIdx.y;
    const int* src; const int* dst; int E; int* cur; int* csr;
    if (rel == 0)      { src = s0; dst = d0; E = E0; cur = g.cur_oo; csr = g.csr_oo; }
    else if (rel == 1) { src = s1; dst = d1; E = E1; cur = g.cur_ro; csr = g.csr_ro; }
    else               { src = s2; dst = d2; E = E2; cur = g.cur_ao; csr = g.csr_ao; }
    int e = blockIdx.x * blockDim.x + threadIdx.x;
    if (e < E) {
        int p = atomicAdd(&cur[dst[e]], 1);
        csr[p] = src[e];
    }
}

// Transpose + pad + bf16-split weights: Wt[n][k] = W[k][n]
__global__ void prep_weights_kernel(const float* __restrict__ W1i,
                                    const float* __restrict__ W1b,
                                    const float* __restrict__ W2) {
    int i = blockIdx.x * blockDim.x + threadIdx.x;
    const int NW1 = HDIM * KPAD1;
    if (i < NW1) {
        int n = i / KPAD1, k = i % KPAD1;
        float wi = (k < F_IN) ? W1i[k * HDIM + n] : 0.f;
        float wb = (k < F_IN) ? W1b[k * HDIM + n] : 0.f;
        split_bf16(wi, g.w1ih[i], g.w1il[i]);
        split_bf16(wb, g.w1bh[i], g.w1bl[i]);
    } else {
        int j = i - NW1;
        if (j < HDIM * HDIM) {
            int n = j / HDIM, k = j % HDIM;
            split_bf16(W2[k * HDIM + n], g.w2h[j], g.w2l[j]);
        }
    }
}

// ---------------- aggregation --------------------------------------------
__device__ __forceinline__ void fma4(float4& acc, float f, const float4 v) {
    acc.x = fmaf(f, v.x, acc.x); acc.y = fmaf(f, v.y, acc.y);
    acc.z = fmaf(f, v.z, acc.z); acc.w = fmaf(f, v.w, acc.w);
}

// all 3 conv1 relations in one launch: grid (N_OBJ, 3), 80 threads
__global__ void agg_conv1_all(const float4* __restrict__ fo,
                              const float4* __restrict__ fr,
                              const float4* __restrict__ fa) {
    int rel = blockIdx.y;
    const int* off; const int* csr; const float* ns; const float4* feat;
    if (rel == 0)      { off = g.off_oo; csr = g.csr_oo; ns = g.ns_oo; feat = fo; }
    else if (rel == 1) { off = g.off_ro; csr = g.csr_ro; ns = g.ns_ro; feat = fr; }
    else               { off = g.off_ao; csr = g.csr_ao; ns = g.ns_ao; feat = fa; }
    int d = blockIdx.x;
    int c = threadIdx.x;          // 80 threads: 75 data + 5 zero-pad chunks
    float4 acc = {0.f, 0.f, 0.f, 0.f};
    if (c < F4_IN) {
        int beg = off[d], end = off[d + 1];
        int e = beg;
        for (; e + 4 <= end; e += 4) {
            int s0 = csr[e], s1 = csr[e+1], s2 = csr[e+2], s3 = csr[e+3];
            float f0 = ns[s0], f1 = ns[s1], f2 = ns[s2], f3 = ns[s3];
            float4 v0 = feat[(size_t)s0 * F4_IN + c];
            float4 v1 = feat[(size_t)s1 * F4_IN + c];
            float4 v2 = feat[(size_t)s2 * F4_IN + c];
            float4 v3 = feat[(size_t)s3 * F4_IN + c];
            fma4(acc, f0, v0); fma4(acc, f1, v1); fma4(acc, f2, v2); fma4(acc, f3, v3);
        }
        for (; e < end; e++) {
            int s = csr[e];
            fma4(acc, ns[s], feat[(size_t)s * F4_IN + c]);
        }
    }
    size_t base = (size_t)rel * N_OBJ * KPAD1 + (size_t)d * KPAD1 + c * 4;
    __nv_bfloat16 h[4], l[4];
    split_bf16(acc.x, h[0], l[0]); split_bf16(acc.y, h[1], l[1]);
    split_bf16(acc.z, h[2], l[2]); split_bf16(acc.w, h[3], l[3]);
    *(uint2*)&g.a1h[base] = *(uint2*)h;
    *(uint2*)&g.a1l[base] = *(uint2*)l;
}

__global__ void agg_conv2_kernel() {
    int d = blockIdx.x;
    int c = threadIdx.x;          // 128 threads
    const float4* feat = (const float4*)g.hsrc2;
    int beg = g.off_oo[d], end = g.off_oo[d + 1];
    float4 acc = {0.f, 0.f, 0.f, 0.f};
    int e = beg;
    for (; e + 4 <= end; e += 4) {
        int s0 = g.csr_oo[e], s1 = g.csr_oo[e+1], s2 = g.csr_oo[e+2], s3 = g.csr_oo[e+3];
        float4 v0 = feat[(size_t)s0 * F4_H + c];
        float4 v1 = feat[(size_t)s1 * F4_H + c];
        float4 v2 = feat[(size_t)s2 * F4_H + c];
        float4 v3 = feat[(size_t)s3 * F4_H + c];
        acc.x += v0.x + v1.x + v2.x + v3.x;
        acc.y += v0.y + v1.y + v2.y + v3.y;
        acc.z += v0.z + v1.z + v2.z + v3.z;
        acc.w += v0.w + v1.w + v2.w + v3.w;
    }
    for (; e < end; e++) {
        int s = g.csr_oo[e];
        float4 v = feat[(size_t)s * F4_H + c];
        acc.x += v.x; acc.y += v.y; acc.z += v.z; acc.w += v.w;
    }
    size_t base = (size_t)d * HDIM + c * 4;
    __nv_bfloat16 h[4], l[4];
    split_bf16(acc.x, h[0], l[0]); split_bf16(acc.y, h[1], l[1]);
    split_bf16(acc.z, h[2], l[2]); split_bf16(acc.w, h[3], l[3]);
    *(uint2*)&g.a2h[base] = *(uint2*)h;
    *(uint2*)&g.a2l[base] = *(uint2*)l;
}

// ---------------- mma.sync GEMM core -------------------------------------
// CTA tile 128x128, 8 warps (wr 0..3 = M rows of 32, wc 0..1 = N cols of 64).
// One K-chunk load {Ah, Al, Bh, Bl} (32 KB) feeds 3 split-term MMAs (768 mma):
// AhBh + AhBl + AlBh. cp.async double-buffered.

// stage layout: [Ah 10240][Al 10240][Bh 10240][Bl 10240]
__device__ __forceinline__ void issue_all(
    const __nv_bfloat16* __restrict__ Ah, const __nv_bfloat16* __restrict__ Al,
    const __nv_bfloat16* __restrict__ Bh, const __nv_bfloat16* __restrict__ Bl,
    int lda, int ldb, int bm, int Mv, int bn, int koff, uint32_t sbase, int tid)
{
    #pragma unroll
    for (int j = 0; j < 8; j++) {
        int rem = (j & 1) * 256 + tid;        // 0..511 within tile
        int r = rem >> 2, q = rem & 3;        // row 0..127, 16B quarter
        uint32_t dst = sbase + (j >> 1) * TILEB + (r * ASTRIDE + q * 8) * 2;
        if (j < 4) {
            const __nv_bfloat16* src = (j < 2 ? Ah : Al);
            cp16(dst, src + (size_t)(bm + r) * lda + koff + q * 8,
                 (bm + r < Mv) ? 16 : 0);
        } else {
            const __nv_bfloat16* src = (j < 6 ? Bh : Bl);
            cp16(dst, src + (size_t)(bn + r) * ldb + koff + q * 8, 16);
        }
    }
    asm volatile("cp.async.commit_group;" ::: "memory");
}

__device__ __forceinline__ void compute_chunk(uint32_t sa, uint32_t sb,
                                              int lane, int wr, int wc,
                                              float acc[2][8][4])
{
    uint32_t arow = wr * 32 + ((lane >> 3) & 1) * 8 + (lane & 7);
    uint32_t acol = (lane >> 4) * 8;
    uint32_t abase = sa + (arow * ASTRIDE + acol) * 2;
    uint32_t nrow = wc * 64 + (lane >> 4) * 8 + (lane & 7);
    uint32_t kcol = ((lane >> 3) & 1) * 8;
    uint32_t bbase = sb + (nrow * ASTRIDE + kcol) * 2;

    #pragma unroll
    for (int k16 = 0; k16 < KC; k16 += 16) {
        uint32_t a0[4], a1[4];
        ldsm4(a0, abase + k16 * 2);
        ldsm4(a1, abase + (16 * ASTRIDE + k16) * 2);
        #pragma unroll
        for (int np = 0; np < 4; np++) {
            uint32_t b[4];
            ldsm4(b, bbase + (np * 16 * ASTRIDE + k16) * 2);
            mma16816(acc[0][2*np],     a0, b);
            mma16816(acc[1][2*np],     a1, b);
            mma16816(acc[0][2*np + 1], a0, b + 2);
            mma16816(acc[1][2*np + 1], a1, b + 2);
        }
    }
}

__device__ __forceinline__ void gemm_rel(
    const __nv_bfloat16* __restrict__ Ah, const __nv_bfloat16* __restrict__ Al,
    const __nv_bfloat16* __restrict__ Bh, const __nv_bfloat16* __restrict__ Bl,
    int K, int lda, int ldb, int bm, int Mv, int bn,
    uint32_t s0, float acc[2][8][4])
{
    int tid = threadIdx.x, lane = tid & 31, wr = (tid >> 5) & 3, wc = tid >> 7;
    int nc = K / KC;
    issue_all(Ah, Al, Bh, Bl, lda, ldb, bm, Mv, bn, 0, s0, tid);
    for (int c = 0; c < nc; c++) {
        uint32_t base = s0 + (c & 1) * STAGEB;
        if (c + 1 < nc) {
            issue_all(Ah, Al, Bh, Bl, lda, ldb, bm, Mv, bn, (c + 1) * KC,
                      s0 + ((c + 1) & 1) * STAGEB, tid);
            asm volatile("cp.async.wait_group 1;" ::: "memory");
        } else {
            asm volatile("cp.async.wait_group 0;" ::: "memory");
        }
        __syncthreads();
        compute_chunk(base,         base + 2 * TILEB, lane, wr, wc, acc);  // AhBh
        compute_chunk(base,         base + 3 * TILEB, lane, wr, wc, acc);  // AhBl
        compute_chunk(base + TILEB, base + 2 * TILEB, lane, wr, wc, acc);  // AlBh
        __syncthreads();
    }
}

// conv1: hsrc2[m,n] = (ns_oo[m]/3) * sum_rel relu(nd_rel[m]*(A_rel@W_rel)[n] + b_rel[n])
__global__ __launch_bounds__(256) void gemm_conv1_mma(
    const float* __restrict__ b1i, const float* __restrict__ b1b)
{
    extern __shared__ char smem_dyn[];
    uint32_t s0 = smem_u32(smem_dyn);
    int bm = blockIdx.x * 128, bn = blockIdx.y * 128;
    int tid = threadIdx.x, lane = tid & 31, wr = (tid >> 5) & 3, wc = tid >> 7;

    float res[2][8][4] = {};

    for (int rel = 0; rel < 3; rel++) {
        const __nv_bfloat16* Ah = g.a1h + (size_t)rel * N_OBJ * KPAD1;
        const __nv_bfloat16* Al = g.a1l + (size_t)rel * N_OBJ * KPAD1;
        const __nv_bfloat16* Bh = (rel == 2) ? g.w1bh : g.w1ih;
        const __nv_bfloat16* Bl = (rel == 2) ? g.w1bl : g.w1il;
        const float* nd   = (rel == 0) ? g.nd_oo : (rel == 1) ? g.nd_ro : g.nd_ao;
        const float* bias = (rel == 2) ? b1b : b1i;

        float acc[2][8][4] = {};
        gemm_rel(Ah, Al, Bh, Bl, KPAD1, KPAD1, KPAD1, bm, N_OBJ, bn, s0, acc);

        #pragma unroll
        for (int mt = 0; mt < 2; mt++) {
            int m0 = bm + wr * 32 + mt * 16 + (lane >> 2);
            int m1 = m0 + 8;
            float nd0 = (m0 < N_OBJ) ? nd[m0] : 0.f;
            float nd1 = (m1 < N_OBJ) ? nd[m1] : 0.f;
            #pragma unroll
            for (int nt = 0; nt < 8; nt++) {
                int col = bn + wc * 64 + nt * 8 + (lane & 3) * 2;
                float bx = bias[col], by = bias[col + 1];
                res[mt][nt][0] += fmaxf(fmaf(acc[mt][nt][0], nd0, bx), 0.f);
                res[mt][nt][1] += fmaxf(fmaf(acc[mt][nt][1], nd0, by), 0.f);
                res[mt][nt][2] += fmaxf(fmaf(acc[mt][nt][2], nd1, bx), 0.f);
                res[mt][nt][3] += fmaxf(fmaf(acc[mt][nt][3], nd1, by), 0.f);
            }
        }
    }

    #pragma unroll
    for (int mt = 0; mt < 2; mt++) {
        int m0 = bm + wr * 32 + mt * 16 + (lane >> 2);
        int m1 = m0 + 8;
        float sc0 = (m0 < N_OBJ) ? g.ns_oo[m0] * (1.f / 3.f) : 0.f;
        float sc1 = (m1 < N_OBJ) ? g.ns_oo[m1] * (1.f / 3.f) : 0.f;
        #pragma unroll
        for (int nt = 0; nt < 8; nt++) {
            int col = bn + wc * 64 + nt * 8 + (lane & 3) * 2;
            if (m0 < N_OBJ)
                *(float2*)&g.hsrc2[(size_t)m0 * HDIM + col] =
                    make_float2(res[mt][nt][0] * sc0, res[mt][nt][1] * sc0);
            if (m1 < N_OBJ)
                *(float2*)&g.hsrc2[(size_t)m1 * HDIM + col] =
                    make_float2(res[mt][nt][2] * sc1, res[mt][nt][3] * sc1);
        }
    }
}

// conv2: out[b,m,n] = nd_oo[m]*(A2@W2)[n] + b2[n], broadcast over b
__global__ __launch_bounds__(256) void gemm_conv2_mma(
    const float* __restrict__ b2, float* __restrict__ out, int B)
{
    extern __shared__ char smem_dyn[];
    uint32_t s0 = smem_u32(smem_dyn);
    int bm = blockIdx.x * 128, bn = blockIdx.y * 128;
    int tid = threadIdx.x, lane = tid & 31, wr = (tid >> 5) & 3, wc = tid >> 7;

    float acc[2][8][4] = {};
    gemm_rel(g.a2h, g.a2l, g.w2h, g.w2l, HDIM, HDIM, HDIM, bm, N_OBJ, bn, s0, acc);

    #pragma unroll
    for (int mt = 0; mt < 2; mt++) {
        int m0 = bm + wr * 32 + mt * 16 + (lane >> 2);
        int m1 = m0 + 8;
        float nd0 = (m0 < N_OBJ) ? g.nd_oo[m0] : 0.f;
        float nd1 = (m1 < N_OBJ) ? g.nd_oo[m1] : 0.f;
        #pragma unroll
        for (int nt = 0; nt < 8; nt++) {
            int col = bn + wc * 64 + nt * 8 + (lane & 3) * 2;
            float bx = b2[col], by = b2[col + 1];
            float2 v0 = make_float2(fmaf(acc[mt][nt][0], nd0, bx),
                                    fmaf(acc[mt][nt][1], nd0, by));
            float2 v1 = make_float2(fmaf(acc[mt][nt][2], nd1, bx),
                                    fmaf(acc[mt][nt][3], nd1, by));
            for (int b = 0; b < B; b++) {
                if (m0 < N_OBJ)
                    *(float2*)&out[(((size_t)b * N_OBJ) + m0) * HDIM + col] = v0;
                if (m1 < N_OBJ)
                    *(float2*)&out[(((size_t)b * N_OBJ) + m1) * HDIM + col] = v1;
            }
        }
    }
}

// ---------------- launch --------------------------------------------------
extern "C" void kernel_launch(void* const* d_in, const int* in_sizes, int n_in,
                              void* d_out, int out_size) {
    const float* feat_obj  = (const float*)d_in[1];
    const float* feat_room = (const float*)d_in[2];
    const float* feat_attr = (const float*)d_in[3];
    const float* W1i = (const float*)d_in[4];
    const float* b1i = (const float*)d_in[5];
    const float* W1b = (const float*)d_in[6];
    const float* b1b = (const float*)d_in[7];
    const float* W2  = (const float*)d_in[8];
    const float* b2  = (const float*)d_in[9];
    const int* src_oo = (const int*)d_in[10];
    const int* dst_oo = (const int*)d_in[11];
    const int* src_ro = (const int*)d_in[12];
    const int* dst_ro = (const int*)d_in[13];
    const int* src_ao = (const int*)d_in[14];
    const int* dst_ao = (const int*)d_in[15];
    int E_oo = in_sizes[10], E_ro = in_sizes[12], E_ao = in_sizes[14];
    float* out = (float*)d_out;
    int B = out_size / (N_OBJ * HDIM);

    cudaFuncSetAttribute(gemm_conv1_mma, cudaFuncAttributeMaxDynamicSharedMemorySize, SMEM_PIPE);
    cudaFuncSetAttribute(gemm_conv2_mma, cudaFuncAttributeMaxDynamicSharedMemorySize, SMEM_PIPE);

    // degrees + norms (merged launches)
    zero_degs_kernel<<<(N_OBJ + 255) / 256, 256>>>();
    dim3 cg((E_oo + 255) / 256, 3);
    count_deg_all<<<cg, 256>>>(src_oo, dst_oo, E_oo, src_ro, dst_ro, E_ro,
                               src_ao, dst_ao, E_ao);
    compute_norms_kernel<<<(N_OBJ + 255) / 256, 256>>>();

    // CSR build
    scan_offsets_all<<<3, 1024>>>();
    fill_csr_all<<<cg, 256>>>(src_oo, dst_oo, E_oo, src_ro, dst_ro, E_ro,
                              src_ao, dst_ao, E_ao);

    // weight transpose + bf16 split
    int prep_n = HDIM * KPAD1 + HDIM * HDIM;
    prep_weights_kernel<<<(prep_n + 255) / 256, 256>>>(W1i, W1b, W2);

    // conv1: aggregate (all relations in one grid) then fused split-term GEMM
    agg_conv1_all<<<dim3(N_OBJ, 3), 80>>>((const float4*)feat_obj,
                                          (const float4*)feat_room,
                                          (const float4*)feat_attr);
    dim3 ggrid((N_OBJ + 127) / 128, HDIM / 128);
    gemm_conv1_mma<<<ggrid, 256, SMEM_PIPE>>>(b1i, b1b);

    // conv2: aggregate then GEMM + broadcast epilogue
    agg_conv2_kernel<<<N_OBJ, 128>>>();
    gemm_conv2_mma<<<ggrid, 256, SMEM_PIPE>>>(b2, out, B);
}